// round 2
// baseline (speedup 1.0000x reference)
#include <cuda_runtime.h>
#include <math.h>

// ---------------- fixed shapes ----------------
#define TKN   4096          // B*L tokens
#define NB    2
#define LSEQ  2048
#define DM    4096          // d_model
#define DXB   1024
#define DIN   4096          // d_inner
#define NH    32            // heads
#define HP    128           // headdim P
#define HN    128           // dstate N
#define PROJ  10272         // 2*DIN + 2*DXB + NH
#define CONVD 6144          // 2*DXB + DIN
#define INTERD 14336
#define NCH   16            // chunks per batch (2048/128)
#define NBLK  (NB*NCH*NH)   // 1024 ssd blocks

// ---------------- scratch (static device globals; no allocations) ----------------
__device__ float d_hnorm[TKN*DM];
__device__ float d_zx[TKN*PROJ];
__device__ float d_xbc[TKN*CONVD];
__device__ float d_dt[TKN*NH];
__device__ float d_av[TKN*NH];
__device__ float d_cs[NBLK*128];
__device__ float d_gm[NBLK];
__device__ float d_states[(size_t)NBLK*HP*HN];
__device__ float d_prev[(size_t)NBLK*HP*HN];
__device__ float d_Y[TKN*DIN];
__device__ float d_h[TKN*DM];
__device__ float d_h2[TKN*DM];
__device__ float d_ga[(size_t)TKN*INTERD];
__device__ float d_up[(size_t)TKN*INTERD];

// ---------------- RMSNorm ----------------
__global__ void rmsnorm_k(const float* __restrict__ x, const float* __restrict__ w,
                          float* __restrict__ o)
{
    int t = blockIdx.x;
    const float* xr = x + (size_t)t*DM;
    float s = 0.f;
    for (int i = threadIdx.x; i < DM; i += 256) { float v = xr[i]; s += v*v; }
    __shared__ float red[256];
    red[threadIdx.x] = s; __syncthreads();
    for (int st = 128; st > 0; st >>= 1) {
        if (threadIdx.x < st) red[threadIdx.x] += red[threadIdx.x + st];
        __syncthreads();
    }
    float inv = rsqrtf(red[0] / (float)DM + 1e-5f);
    float* orow = o + (size_t)t*DM;
    for (int i = threadIdx.x; i < DM; i += 256) orow[i] = xr[i]*inv*w[i];
}

// ---------------- GEMM: C[M,N] = A[M,K] * B[N,K]^T (+Res) ----------------
// M = 4096 (exact multiple of 128). N guarded. K multiple of 16.
__global__ void __launch_bounds__(256)
gemm_nt(const float* __restrict__ A, const float* __restrict__ B,
        const float* __restrict__ Res, float* __restrict__ C,
        int N, int K)
{
    __shared__ float As[16][132];
    __shared__ float Bs[16][132];
    const int bm = blockIdx.y << 7, bn = blockIdx.x << 7;
    const int tid = threadIdx.x;
    const int tx = tid & 15, ty = tid >> 4;
    float acc[8][8];
    #pragma unroll
    for (int i = 0; i < 8; i++)
        #pragma unroll
        for (int j = 0; j < 8; j++) acc[i][j] = 0.f;

    for (int k0 = 0; k0 < K; k0 += 16) {
        #pragma unroll
        for (int it = 0; it < 2; it++) {
            int idx = it*256 + tid;            // 0..511 float4 slots
            int row = idx >> 2;
            int c4  = (idx & 3) << 2;
            float4 va = *reinterpret_cast<const float4*>(A + (size_t)(bm+row)*K + k0 + c4);
            As[c4+0][row] = va.x; As[c4+1][row] = va.y;
            As[c4+2][row] = va.z; As[c4+3][row] = va.w;
            int brow = bn + row;
            float4 vb = make_float4(0.f,0.f,0.f,0.f);
            if (brow < N)
                vb = *reinterpret_cast<const float4*>(B + (size_t)brow*K + k0 + c4);
            Bs[c4+0][row] = vb.x; Bs[c4+1][row] = vb.y;
            Bs[c4+2][row] = vb.z; Bs[c4+3][row] = vb.w;
        }
        __syncthreads();
        #pragma unroll
        for (int kk = 0; kk < 16; kk++) {
            float ar[8], br[8];
            *reinterpret_cast<float4*>(ar)   = *reinterpret_cast<const float4*>(&As[kk][ty*8]);
            *reinterpret_cast<float4*>(ar+4) = *reinterpret_cast<const float4*>(&As[kk][ty*8+4]);
            *reinterpret_cast<float4*>(br)   = *reinterpret_cast<const float4*>(&Bs[kk][tx*8]);
            *reinterpret_cast<float4*>(br+4) = *reinterpret_cast<const float4*>(&Bs[kk][tx*8+4]);
            #pragma unroll
            for (int i = 0; i < 8; i++)
                #pragma unroll
                for (int j = 0; j < 8; j++)
                    acc[i][j] = fmaf(ar[i], br[j], acc[i][j]);
        }
        __syncthreads();
    }
    #pragma unroll
    for (int i = 0; i < 8; i++) {
        int m = bm + ty*8 + i;
        #pragma unroll
        for (int j = 0; j < 8; j++) {
            int n = bn + tx*8 + j;
            if (n < N) {
                float v = acc[i][j];
                if (Res) v += Res[(size_t)m*N + n];
                C[(size_t)m*N + n] = v;
            }
        }
    }
}

// ---------------- depthwise causal conv1d + SiLU ----------------
// xBC = columns [4096, 10240) of zxbcdt (xs|Bs|Cs are contiguous there)
__global__ void conv_k(const float* __restrict__ zx, const float* __restrict__ cw,
                       const float* __restrict__ cb, float* __restrict__ xbc)
{
    int c = blockIdx.x*256 + threadIdx.x;   // < 6144
    int t = blockIdx.y;
    int l = t & (LSEQ - 1);
    const float* base = zx + (size_t)t*PROJ + 4096 + c;
    float w0 = cw[c*4+0], w1 = cw[c*4+1], w2 = cw[c*4+2], w3 = cw[c*4+3];
    float acc = cb[c] + w3*base[0];
    if (l >= 1) acc += w2*base[-(ptrdiff_t)PROJ];
    if (l >= 2) acc += w1*base[-(ptrdiff_t)(2*PROJ)];
    if (l >= 3) acc += w0*base[-(ptrdiff_t)(3*PROJ)];
    float sv = acc / (1.f + expf(-acc));
    xbc[(size_t)t*CONVD + c] = sv;
}

// ---------------- dt = softplus(dt_raw + bias), a = dt * (-exp(A_log)) ----------------
__global__ void dt_k(const float* __restrict__ zx, const float* __restrict__ dtb,
                     const float* __restrict__ Alog, float* __restrict__ dto,
                     float* __restrict__ ao)
{
    int idx = blockIdx.x*256 + threadIdx.x;
    if (idx >= TKN*NH) return;
    int t = idx >> 5, h = idx & 31;
    float raw = zx[(size_t)t*PROJ + 10240 + h] + dtb[h];
    float dt = (raw > 20.f) ? raw : log1pf(expf(raw));
    dto[idx] = dt;
    ao[idx]  = -expf(Alog[h]) * dt;
}

// ---------------- SSD stage 1: per (b,chunk,head) ----------------
// computes cs (cumsum), g=exp(cs[127]), att=C·B^T·L·dt, Yd=att·X (+D·x), states=X^T·diag(w)·B
__global__ void __launch_bounds__(256)
ssd1_k(const float* __restrict__ xbc, const float* __restrict__ dtv,
       const float* __restrict__ av, const float* __restrict__ Dv,
       float* __restrict__ Y, float* __restrict__ cso,
       float* __restrict__ gmo, float* __restrict__ states)
{
    extern __shared__ float sm[];
    float* att = sm;                 // 128*129 = 16512
    float* t1  = att + 128*129;      // 4224
    float* t2  = t1 + 4224;          // 4224
    float* cs  = t2 + 4224;          // 128
    float* dts = cs + 128;           // 128
    __shared__ float wsum[4];

    int blk = blockIdx.x;
    int h = blk & 31, ch = (blk >> 5) & 15, b = blk >> 9;
    int t0 = b*LSEQ + ch*128;
    int g  = h >> 2;
    int tid = threadIdx.x;
    int tx = tid & 15, ty = tid >> 4;

    // cumsum of a over the chunk (warp scans + cross-warp fixup)
    float v = 0.f;
    if (tid < 128) {
        dts[tid] = dtv[(size_t)(t0+tid)*NH + h];
        v = av[(size_t)(t0+tid)*NH + h];
        #pragma unroll
        for (int off = 1; off < 32; off <<= 1) {
            float n = __shfl_up_sync(0xffffffffu, v, off);
            if ((tid & 31) >= off) v += n;
        }
        if ((tid & 31) == 31) wsum[tid >> 5] = v;
    }
    __syncthreads();
    if (tid < 128) {
        float add = 0.f;
        for (int w = 0; w < (tid >> 5); w++) add += wsum[w];
        float c = v + add;
        cs[tid] = c;
        cso[blk*128 + tid] = c;
    }
    __syncthreads();
    if (tid == 0) gmo[blk] = expf(cs[127]);

    const float* Cbase = xbc + 2048 + h*128;
    const float* Bbase = xbc + 1024 + g*128;
    const float* Xbase = xbc + g*128;

    // ---- matmul 1: att[q,k] = sum_n C[q,n]*B[k,n] ----
    float acc[8][8];
    #pragma unroll
    for (int i = 0; i < 8; i++)
        #pragma unroll
        for (int j = 0; j < 8; j++) acc[i][j] = 0.f;
    for (int nt = 0; nt < 4; nt++) {
        #pragma unroll
        for (int i = 0; i < 16; i++) {
            int idx = tid + i*256;          // 0..4095
            int q = idx >> 5, n = idx & 31;
            t1[q*33+n] = Cbase[(size_t)(t0+q)*CONVD + nt*32 + n];
            t2[q*33+n] = Bbase[(size_t)(t0+q)*CONVD + nt*32 + n];
        }
        __syncthreads();
        #pragma unroll
        for (int n = 0; n < 32; n++) {
            float cr[8], br[8];
            #pragma unroll
            for (int i = 0; i < 8; i++) cr[i] = t1[(ty*8+i)*33 + n];
            #pragma unroll
            for (int j = 0; j < 8; j++) br[j] = t2[(tx*8+j)*33 + n];
            #pragma unroll
            for (int i = 0; i < 8; i++)
                #pragma unroll
                for (int j = 0; j < 8; j++)
                    acc[i][j] = fmaf(cr[i], br[j], acc[i][j]);
        }
        __syncthreads();
    }
    // decay mask * dt, stash in smem
    #pragma unroll
    for (int i = 0; i < 8; i++) {
        int q = ty*8 + i;
        #pragma unroll
        for (int j = 0; j < 8; j++) {
            int k = tx*8 + j;
            float f = (q >= k) ? expf(cs[q] - cs[k]) * dts[k] : 0.f;
            att[q*129 + k] = acc[i][j] * f;
        }
    }
    __syncthreads();

    // ---- matmul 2: Yd[q,p] = sum_k att[q,k]*X[k,p]; write Yd + D*x ----
    #pragma unroll
    for (int i = 0; i < 8; i++)
        #pragma unroll
        for (int j = 0; j < 8; j++) acc[i][j] = 0.f;
    for (int kt = 0; kt < 4; kt++) {
        #pragma unroll
        for (int i = 0; i < 16; i++) {
            int idx = tid + i*256;          // 0..4095
            int k = idx >> 7, p = idx & 127;
            t1[k*129 + p] = Xbase[(size_t)(t0 + kt*32 + k)*CONVD + p];
        }
        __syncthreads();
        #pragma unroll
        for (int k = 0; k < 32; k++) {
            float ar[8], xr[8];
            #pragma unroll
            for (int i = 0; i < 8; i++) ar[i] = att[(ty*8+i)*129 + kt*32 + k];
            #pragma unroll
            for (int j = 0; j < 8; j++) xr[j] = t1[k*129 + tx*8 + j];
            #pragma unroll
            for (int i = 0; i < 8; i++)
                #pragma unroll
                for (int j = 0; j < 8; j++)
                    acc[i][j] = fmaf(ar[i], xr[j], acc[i][j]);
        }
        __syncthreads();
    }
    float Dh = Dv[h];
    #pragma unroll
    for (int i = 0; i < 8; i++) {
        int q = ty*8 + i; int trow = t0 + q;
        #pragma unroll
        for (int j = 0; j < 8; j++) {
            int p = tx*8 + j;
            float xv = Xbase[(size_t)trow*CONVD + p];
            Y[(size_t)trow*DIN + h*128 + p] = acc[i][j] + Dh*xv;
        }
    }
    __syncthreads();

    // ---- matmul 3: states[p,n] = sum_q w[q]*X[q,p]*B[q,n] ----
    #pragma unroll
    for (int i = 0; i < 8; i++)
        #pragma unroll
        for (int j = 0; j < 8; j++) acc[i][j] = 0.f;
    float clast = cs[127];
    for (int qt = 0; qt < 4; qt++) {
        #pragma unroll
        for (int i = 0; i < 16; i++) {
            int idx = tid + i*256;
            int q = idx >> 7, p = idx & 127;
            int qq = qt*32 + q;
            float w = expf(clast - cs[qq]) * dts[qq];
            t1[q*129 + p] = w * Xbase[(size_t)(t0+qq)*CONVD + p];
            t2[q*129 + p] = Bbase[(size_t)(t0+qq)*CONVD + p];
        }
        __syncthreads();
        #pragma unroll
        for (int k = 0; k < 32; k++) {
            float xr[8], br[8];
            #pragma unroll
            for (int i = 0; i < 8; i++) xr[i] = t1[k*129 + ty*8 + i];
            #pragma unroll
            for (int j = 0; j < 8; j++) br[j] = t2[k*129 + tx*8 + j];
            #pragma unroll
            for (int i = 0; i < 8; i++)
                #pragma unroll
                for (int j = 0; j < 8; j++)
                    acc[i][j] = fmaf(xr[i], br[j], acc[i][j]);
        }
        __syncthreads();
    }
    size_t sbase = (size_t)blk*HP*HN;
    #pragma unroll
    for (int i = 0; i < 8; i++)
        #pragma unroll
        for (int j = 0; j < 8; j++)
            states[sbase + (size_t)(ty*8+i)*HN + tx*8 + j] = acc[i][j];
}

// ---------------- inter-chunk recurrence: prev[c] = S; S = g[c]*S + states[c] ----------------
__global__ void scan_k(const float* __restrict__ states, const float* __restrict__ gm,
                       float* __restrict__ prev)
{
    int bh = blockIdx.x;               // 0..63
    int b = bh >> 5, h = bh & 31;
    int e0 = threadIdx.x;              // blockDim 1024
    float S[16];
    #pragma unroll
    for (int e = 0; e < 16; e++) S[e] = 0.f;
    for (int ch = 0; ch < NCH; ch++) {
        int blk = (b*NCH + ch)*NH + h;
        float gv = gm[blk];
        size_t base = (size_t)blk*HP*HN;
        #pragma unroll
        for (int e = 0; e < 16; e++) {
            int idx = e0 + e*1024;
            prev[base + idx] = S[e];
            S[e] = gv*S[e] + states[base + idx];
        }
    }
}

// ---------------- SSD stage 2: Yo[q,p] = exp(cs[q]) * sum_n C[q,n]*prev[p,n]; Y += Yo ----------------
__global__ void __launch_bounds__(256)
ssd2_k(const float* __restrict__ xbc, const float* __restrict__ prev,
       const float* __restrict__ csv, float* __restrict__ Y)
{
    __shared__ float t1[128*33];
    __shared__ float t2[128*33];
    __shared__ float cs[128];
    int blk = blockIdx.x;
    int h = blk & 31, ch = (blk >> 5) & 15, b = blk >> 9;
    int t0 = b*LSEQ + ch*128;
    int tid = threadIdx.x, tx = tid & 15, ty = tid >> 4;
    if (tid < 128) cs[tid] = csv[blk*128 + tid];
    float acc[8][8];
    #pragma unroll
    for (int i = 0; i < 8; i++)
        #pragma unroll
        for (int j = 0; j < 8; j++) acc[i][j] = 0.f;
    const float* Cbase = xbc + 2048 + h*128;
    size_t pbase = (size_t)blk*HP*HN;
    for (int nt = 0; nt < 4; nt++) {
        #pragma unroll
        for (int i = 0; i < 16; i++) {
            int idx = tid + i*256;
            int r = idx >> 5, n = idx & 31;
            t1[r*33+n] = Cbase[(size_t)(t0+r)*CONVD + nt*32 + n];
            t2[r*33+n] = prev[pbase + (size_t)r*HN + nt*32 + n];
        }
        __syncthreads();
        #pragma unroll
        for (int n = 0; n < 32; n++) {
            float cr[8], pr[8];
            #pragma unroll
            for (int i = 0; i < 8; i++) cr[i] = t1[(ty*8+i)*33 + n];
            #pragma unroll
            for (int j = 0; j < 8; j++) pr[j] = t2[(tx*8+j)*33 + n];
            #pragma unroll
            for (int i = 0; i < 8; i++)
                #pragma unroll
                for (int j = 0; j < 8; j++)
                    acc[i][j] = fmaf(cr[i], pr[j], acc[i][j]);
        }
        __syncthreads();
    }
    #pragma unroll
    for (int i = 0; i < 8; i++) {
        int q = ty*8 + i;
        float eq = expf(cs[q]);
        #pragma unroll
        for (int j = 0; j < 8; j++) {
            int p = tx*8 + j;
            size_t off = (size_t)(t0+q)*DIN + h*128 + p;
            Y[off] += eq * acc[i][j];
        }
    }
}

// ---------------- y = Y * silu(z) ----------------
__global__ void gate_y_k(const float* __restrict__ zx, float* __restrict__ Y)
{
    int idx = blockIdx.x*256 + threadIdx.x;    // T*DIN
    int t = idx >> 12, d = idx & 4095;
    float z = zx[(size_t)t*PROJ + d];
    float s = z / (1.f + expf(-z));
    Y[idx] *= s;
}

// ---------------- act = silu(gate) * up ----------------
__global__ void act_k(float* __restrict__ ga, const float* __restrict__ up)
{
    size_t idx = (size_t)blockIdx.x*256 + threadIdx.x;
    float gv = ga[idx];
    ga[idx] = (gv / (1.f + expf(-gv))) * up[idx];
}

// ---------------- launcher ----------------
extern "C" void kernel_launch(void* const* d_in, const int* in_sizes, int n_in,
                              void* d_out, int out_size)
{
    const float* hidden = (const float*)d_in[0];
    const float* w_in   = (const float*)d_in[1];
    const float* conv_w = (const float*)d_in[2];
    const float* conv_b = (const float*)d_in[3];
    const float* A_log  = (const float*)d_in[4];
    const float* Dv     = (const float*)d_in[5];
    const float* dt_b   = (const float*)d_in[6];
    const float* w_out  = (const float*)d_in[7];
    const float* ln1    = (const float*)d_in[8];
    const float* ln2    = (const float*)d_in[9];
    const float* gate_w = (const float*)d_in[10];
    const float* up_w   = (const float*)d_in[11];
    const float* down_w = (const float*)d_in[12];
    float* out = (float*)d_out;

    float *hnorm, *zx, *xbc, *dt, *av, *cs, *gm, *st, *pv, *Y, *h, *h2, *ga, *up;
    cudaGetSymbolAddress((void**)&hnorm, d_hnorm);
    cudaGetSymbolAddress((void**)&zx,    d_zx);
    cudaGetSymbolAddress((void**)&xbc,   d_xbc);
    cudaGetSymbolAddress((void**)&dt,    d_dt);
    cudaGetSymbolAddress((void**)&av,    d_av);
    cudaGetSymbolAddress((void**)&cs,    d_cs);
    cudaGetSymbolAddress((void**)&gm,    d_gm);
    cudaGetSymbolAddress((void**)&st,    d_states);
    cudaGetSymbolAddress((void**)&pv,    d_prev);
    cudaGetSymbolAddress((void**)&Y,     d_Y);
    cudaGetSymbolAddress((void**)&h,     d_h);
    cudaGetSymbolAddress((void**)&h2,    d_h2);
    cudaGetSymbolAddress((void**)&ga,    d_ga);
    cudaGetSymbolAddress((void**)&up,    d_up);

    // 1) pre-norm
    rmsnorm_k<<<TKN, 256>>>(hidden, ln1, hnorm);
    // 2) in_proj: zx[T,10272] = hnorm @ w_in^T
    gemm_nt<<<dim3(81, 32), 256>>>(hnorm, w_in, nullptr, zx, PROJ, DM);
    // 3) depthwise causal conv + SiLU over [x|B|C] (zx columns 4096..10240)
    conv_k<<<dim3(24, TKN), 256>>>(zx, conv_w, conv_b, xbc);
    // 4) dt / a
    dt_k<<<(TKN*NH)/256, 256>>>(zx, dt_b, A_log, dt, av);
    // 5) SSD stage 1 (intra-chunk)
    int smem1 = (128*129 + 4224 + 4224 + 128 + 128) * 4;   // 100,864 B
    cudaFuncSetAttribute(ssd1_k, cudaFuncAttributeMaxDynamicSharedMemorySize, smem1);
    ssd1_k<<<NBLK, 256, smem1>>>(xbc, dt, av, Dv, Y, cs, gm, st);
    // 6) inter-chunk recurrence
    scan_k<<<NB*NH, 1024>>>(st, gm, pv);
    // 7) SSD stage 2 (inter-chunk output)
    ssd2_k<<<NBLK, 256>>>(xbc, pv, cs, Y);
    // 8) gate with silu(z)
    gate_y_k<<<(TKN*DIN)/256, 256>>>(zx, Y);
    // 9) out_proj + residual -> h
    gemm_nt<<<dim3(32, 32), 256>>>(Y, w_out, hidden, h, DM, DIN);
    // 10) second norm
    rmsnorm_k<<<TKN, 256>>>(h, ln2, h2);
    // 11) MLP
    gemm_nt<<<dim3(112, 32), 256>>>(h2, gate_w, nullptr, ga, INTERD, DM);
    gemm_nt<<<dim3(112, 32), 256>>>(h2, up_w,   nullptr, up, INTERD, DM);
    act_k<<<((size_t)TKN*INTERD)/256, 256>>>(ga, up);
    // 12) down_proj + residual -> out
    gemm_nt<<<dim3(32, 32), 256>>>(ga, down_w, h, out, DM, INTERD);
}

// round 4
// speedup vs baseline: 3.9741x; 3.9741x over previous
#include <cuda_runtime.h>
#include <math.h>
#include <stdint.h>

// ---------------- fixed shapes ----------------
#define TKN   4096          // B*L tokens
#define NB    2
#define LSEQ  2048
#define DM    4096          // d_model
#define DXB   1024
#define DIN   4096          // d_inner
#define NH    32            // heads
#define HP    128           // headdim P
#define HN    128           // dstate N
#define PROJ  10272         // 2*DIN + 2*DXB + NH
#define CONVD 6144          // 2*DXB + DIN
#define INTERD 14336
#define NCH   16            // chunks per batch (2048/128)
#define NBLK  (NB*NCH*NH)   // 1024 ssd blocks

// ---------------- scratch (static device globals; no allocations) ----------------
__device__ float d_hnorm[TKN*DM];
__device__ float d_zx[TKN*PROJ];
__device__ float d_xbc[TKN*CONVD];
__device__ float d_dt[TKN*NH];
__device__ float d_av[TKN*NH];
__device__ float d_cs[NBLK*128];
__device__ float d_gm[NBLK];
__device__ float d_states[(size_t)NBLK*HP*HN];
__device__ float d_prev[(size_t)NBLK*HP*HN];
__device__ float d_Y[TKN*DIN];
__device__ float d_h[TKN*DM];
__device__ float d_h2[TKN*DM];
__device__ float d_ga[(size_t)TKN*INTERD];
__device__ float d_up[(size_t)TKN*INTERD];

// tf32 round-to-nearest helpers
static __device__ __forceinline__ float tf32r(float x) {
    uint32_t u; asm("cvt.rna.tf32.f32 %0, %1;" : "=r"(u) : "f"(x));
    return __uint_as_float(u);
}
static __device__ __forceinline__ uint32_t cvt_tf32(float x) {
    uint32_t u; asm("cvt.rna.tf32.f32 %0, %1;" : "=r"(u) : "f"(x));
    return u;
}

// ================= tf32 mma.sync GEMM =================
// C[M,N] = A[M,K] @ B[N,K]^T (+Res). M mult of 128, K mult of 32, N even (guarded).
// A is assumed already tf32-rounded (done at producers); B rounded in-register.
// Tile 128x128, BK=32, 3-stage cp.async pipeline. 8 warps (2m x 4n), warp tile 64x32.

#define GSMEM_DYN (3*32768)

__global__ void __launch_bounds__(256)
gemm_mma(const float* __restrict__ A, const float* __restrict__ Bw,
         const float* __restrict__ Res, float* __restrict__ C,
         int N, int K)
{
    extern __shared__ char smraw[];
    const int tid  = threadIdx.x;
    const int lane = tid & 31, warp = tid >> 5;
    const int wm = warp & 1, wn = warp >> 1;        // 2 x 4 warp grid
    const int bm = blockIdx.y << 7, bn = blockIdx.x << 7;
    const int T = K >> 5;
    uint32_t sbase = (uint32_t)__cvta_generic_to_shared(smraw);

    // stage layout: A 16KB (128 rows x 128B, 16B-chunk swizzled), B 16KB same
    auto load_tile = [&](int t) {
        uint32_t s = sbase + (uint32_t)(t % 3) * 32768u;
        int k0 = t << 5;
        #pragma unroll
        for (int i = 0; i < 4; i++) {
            int idx = i*256 + tid, row = idx >> 3, c = idx & 7;
            uint32_t dst = s + row*128 + (uint32_t)((c ^ (row & 7)) << 4);
            asm volatile("cp.async.cg.shared.global [%0], [%1], 16;"
                         :: "r"(dst), "l"(A + (size_t)(bm + row)*K + k0 + c*4));
        }
        #pragma unroll
        for (int i = 0; i < 4; i++) {
            int idx = i*256 + tid, row = idx >> 3, c = idx & 7;
            int brow = bn + row; if (brow >= N) brow = N - 1;
            uint32_t dst = s + 16384u + row*128 + (uint32_t)((c ^ (row & 7)) << 4);
            asm volatile("cp.async.cg.shared.global [%0], [%1], 16;"
                         :: "r"(dst), "l"(Bw + (size_t)brow*K + k0 + c*4));
        }
    };

    float acc[4][4][4];
    #pragma unroll
    for (int a = 0; a < 4; a++)
        #pragma unroll
        for (int b = 0; b < 4; b++)
            #pragma unroll
            for (int c = 0; c < 4; c++) acc[a][b][c] = 0.f;

    load_tile(0);
    asm volatile("cp.async.commit_group;" ::: "memory");
    load_tile(1);
    asm volatile("cp.async.commit_group;" ::: "memory");

    for (int t = 0; t < T; t++) {
        if (t + 2 < T) load_tile(t + 2);
        asm volatile("cp.async.commit_group;" ::: "memory");
        asm volatile("cp.async.wait_group 2;" ::: "memory");
        __syncthreads();

        uint32_t as = sbase + (uint32_t)(t % 3) * 32768u;
        uint32_t bs = as + 16384u;

        #pragma unroll
        for (int kk = 0; kk < 4; kk++) {
            // A fragments: 4 m-tiles via ldmatrix.x4 (swizzle keeps it conflict-free)
            uint32_t af[4][4];
            #pragma unroll
            for (int mt = 0; mt < 4; mt++) {
                int m  = wm*64 + mt*16 + (lane & 7) + ((lane >> 3) & 1) * 8;
                int kc = kk*2 + (lane >> 4);
                uint32_t addr = as + m*128 + (uint32_t)((kc ^ (m & 7)) << 4);
                asm volatile("ldmatrix.sync.aligned.m8n8.x4.shared.b16 {%0,%1,%2,%3}, [%4];"
                             : "=r"(af[mt][0]), "=r"(af[mt][1]),
                               "=r"(af[mt][2]), "=r"(af[mt][3]) : "r"(addr));
            }
            #pragma unroll
            for (int nt = 0; nt < 4; nt++) {
                int n = wn*32 + nt*8 + (lane >> 2);
                uint32_t r0 = bs + n*128 + (uint32_t)((((2*kk)  ^ (n & 7)) << 4)) + (lane & 3)*4;
                uint32_t r1 = bs + n*128 + (uint32_t)((((2*kk+1)^ (n & 7)) << 4)) + (lane & 3)*4;
                float f0, f1;
                asm volatile("ld.shared.f32 %0, [%1];" : "=f"(f0) : "r"(r0));
                asm volatile("ld.shared.f32 %0, [%1];" : "=f"(f1) : "r"(r1));
                uint32_t b0 = cvt_tf32(f0), b1 = cvt_tf32(f1);
                #pragma unroll
                for (int mt = 0; mt < 4; mt++) {
                    asm volatile(
                        "mma.sync.aligned.m16n8k8.row.col.f32.tf32.tf32.f32 "
                        "{%0,%1,%2,%3}, {%4,%5,%6,%7}, {%8,%9}, {%0,%1,%2,%3};"
                        : "+f"(acc[mt][nt][0]), "+f"(acc[mt][nt][1]),
                          "+f"(acc[mt][nt][2]), "+f"(acc[mt][nt][3])
                        : "r"(af[mt][0]), "r"(af[mt][1]), "r"(af[mt][2]), "r"(af[mt][3]),
                          "r"(b0), "r"(b1));
                }
            }
        }
        __syncthreads();
    }

    // epilogue
    #pragma unroll
    for (int mt = 0; mt < 4; mt++) {
        int r0 = bm + wm*64 + mt*16 + (lane >> 2);
        #pragma unroll
        for (int nt = 0; nt < 4; nt++) {
            int c0 = bn + wn*32 + nt*8 + 2*(lane & 3);
            if (c0 < N) {
                float2 v0 = make_float2(acc[mt][nt][0], acc[mt][nt][1]);
                float2 v1 = make_float2(acc[mt][nt][2], acc[mt][nt][3]);
                if (Res) {
                    float2 q0 = *reinterpret_cast<const float2*>(Res + (size_t)r0*N + c0);
                    float2 q1 = *reinterpret_cast<const float2*>(Res + (size_t)(r0+8)*N + c0);
                    v0.x += q0.x; v0.y += q0.y; v1.x += q1.x; v1.y += q1.y;
                }
                *reinterpret_cast<float2*>(C + (size_t)r0*N + c0)     = v0;
                *reinterpret_cast<float2*>(C + (size_t)(r0+8)*N + c0) = v1;
            }
        }
    }
}

// ---------------- RMSNorm (output tf32-rounded: feeds GEMM A operands) ----------------
__global__ void rmsnorm_k(const float* __restrict__ x, const float* __restrict__ w,
                          float* __restrict__ o)
{
    int t = blockIdx.x;
    const float* xr = x + (size_t)t*DM;
    float s = 0.f;
    for (int i = threadIdx.x; i < DM; i += 256) { float v = xr[i]; s += v*v; }
    __shared__ float red[256];
    red[threadIdx.x] = s; __syncthreads();
    for (int st = 128; st > 0; st >>= 1) {
        if (threadIdx.x < st) red[threadIdx.x] += red[threadIdx.x + st];
        __syncthreads();
    }
    float inv = rsqrtf(red[0] / (float)DM + 1e-5f);
    float* orow = o + (size_t)t*DM;
    for (int i = threadIdx.x; i < DM; i += 256) orow[i] = tf32r(xr[i]*inv*w[i]);
}

// ---------------- depthwise causal conv1d + SiLU ----------------
__global__ void conv_k(const float* __restrict__ zx, const float* __restrict__ cw,
                       const float* __restrict__ cb, float* __restrict__ xbc)
{
    int c = blockIdx.x*256 + threadIdx.x;   // < 6144
    int t = blockIdx.y;
    int l = t & (LSEQ - 1);
    const float* base = zx + (size_t)t*PROJ + 4096 + c;
    float w0 = cw[c*4+0], w1 = cw[c*4+1], w2 = cw[c*4+2], w3 = cw[c*4+3];
    float acc = cb[c] + w3*base[0];
    if (l >= 1) acc += w2*base[-(ptrdiff_t)PROJ];
    if (l >= 2) acc += w1*base[-(ptrdiff_t)(2*PROJ)];
    if (l >= 3) acc += w0*base[-(ptrdiff_t)(3*PROJ)];
    float sv = acc / (1.f + expf(-acc));
    xbc[(size_t)t*CONVD + c] = sv;
}

// ---------------- dt = softplus(dt_raw + bias), a = dt * (-exp(A_log)) ----------------
__global__ void dt_k(const float* __restrict__ zx, const float* __restrict__ dtb,
                     const float* __restrict__ Alog, float* __restrict__ dto,
                     float* __restrict__ ao)
{
    int idx = blockIdx.x*256 + threadIdx.x;
    if (idx >= TKN*NH) return;
    int t = idx >> 5, h = idx & 31;
    float raw = zx[(size_t)t*PROJ + 10240 + h] + dtb[h];
    float dt = (raw > 20.f) ? raw : log1pf(expf(raw));
    dto[idx] = dt;
    ao[idx]  = -expf(Alog[h]) * dt;
}

// ---------------- SSD stage 1: per (b,chunk,head) ----------------
__global__ void __launch_bounds__(256)
ssd1_k(const float* __restrict__ xbc, const float* __restrict__ dtv,
       const float* __restrict__ av, const float* __restrict__ Dv,
       float* __restrict__ Y, float* __restrict__ cso,
       float* __restrict__ gmo, float* __restrict__ states)
{
    extern __shared__ float sm[];
    float* att = sm;                 // 128*129 = 16512
    float* t1  = att + 128*129;      // 4224
    float* t2  = t1 + 4224;          // 4224
    float* cs  = t2 + 4224;          // 128
    float* dts = cs + 128;           // 128
    __shared__ float wsum[4];

    int blk = blockIdx.x;
    int h = blk & 31, ch = (blk >> 5) & 15, b = blk >> 9;
    int t0 = b*LSEQ + ch*128;
    int g  = h >> 2;
    int tid = threadIdx.x;
    int tx = tid & 15, ty = tid >> 4;

    float v = 0.f;
    if (tid < 128) {
        dts[tid] = dtv[(size_t)(t0+tid)*NH + h];
        v = av[(size_t)(t0+tid)*NH + h];
        #pragma unroll
        for (int off = 1; off < 32; off <<= 1) {
            float n = __shfl_up_sync(0xffffffffu, v, off);
            if ((tid & 31) >= off) v += n;
        }
        if ((tid & 31) == 31) wsum[tid >> 5] = v;
    }
    __syncthreads();
    if (tid < 128) {
        float add = 0.f;
        for (int w = 0; w < (tid >> 5); w++) add += wsum[w];
        float c = v + add;
        cs[tid] = c;
        cso[blk*128 + tid] = c;
    }
    __syncthreads();
    if (tid == 0) gmo[blk] = expf(cs[127]);

    const float* Cbase = xbc + 2048 + h*128;
    const float* Bbase = xbc + 1024 + g*128;
    const float* Xbase = xbc + g*128;

    float acc[8][8];
    #pragma unroll
    for (int i = 0; i < 8; i++)
        #pragma unroll
        for (int j = 0; j < 8; j++) acc[i][j] = 0.f;
    for (int nt = 0; nt < 4; nt++) {
        #pragma unroll
        for (int i = 0; i < 16; i++) {
            int idx = tid + i*256;
            int q = idx >> 5, n = idx & 31;
            t1[q*33+n] = Cbase[(size_t)(t0+q)*CONVD + nt*32 + n];
            t2[q*33+n] = Bbase[(size_t)(t0+q)*CONVD + nt*32 + n];
        }
        __syncthreads();
        #pragma unroll
        for (int n = 0; n < 32; n++) {
            float cr[8], br[8];
            #pragma unroll
            for (int i = 0; i < 8; i++) cr[i] = t1[(ty*8+i)*33 + n];
            #pragma unroll
            for (int j = 0; j < 8; j++) br[j] = t2[(tx*8+j)*33 + n];
            #pragma unroll
            for (int i = 0; i < 8; i++)
                #pragma unroll
                for (int j = 0; j < 8; j++)
                    acc[i][j] = fmaf(cr[i], br[j], acc[i][j]);
        }
        __syncthreads();
    }
    #pragma unroll
    for (int i = 0; i < 8; i++) {
        int q = ty*8 + i;
        #pragma unroll
        for (int j = 0; j < 8; j++) {
            int k = tx*8 + j;
            float f = (q >= k) ? expf(cs[q] - cs[k]) * dts[k] : 0.f;
            att[q*129 + k] = acc[i][j] * f;
        }
    }
    __syncthreads();

    #pragma unroll
    for (int i = 0; i < 8; i++)
        #pragma unroll
        for (int j = 0; j < 8; j++) acc[i][j] = 0.f;
    for (int kt = 0; kt < 4; kt++) {
        #pragma unroll
        for (int i = 0; i < 16; i++) {
            int idx = tid + i*256;
            int k = idx >> 7, p = idx & 127;
            t1[k*129 + p] = Xbase[(size_t)(t0 + kt*32 + k)*CONVD + p];
        }
        __syncthreads();
        #pragma unroll
        for (int k = 0; k < 32; k++) {
            float ar[8], xr[8];
            #pragma unroll
            for (int i = 0; i < 8; i++) ar[i] = att[(ty*8+i)*129 + kt*32 + k];
            #pragma unroll
            for (int j = 0; j < 8; j++) xr[j] = t1[k*129 + tx*8 + j];
            #pragma unroll
            for (int i = 0; i < 8; i++)
                #pragma unroll
                for (int j = 0; j < 8; j++)
                    acc[i][j] = fmaf(ar[i], xr[j], acc[i][j]);
        }
        __syncthreads();
    }
    float Dh = Dv[h];
    #pragma unroll
    for (int i = 0; i < 8; i++) {
        int q = ty*8 + i; int trow = t0 + q;
        #pragma unroll
        for (int j = 0; j < 8; j++) {
            int p = tx*8 + j;
            float xv = Xbase[(size_t)trow*CONVD + p];
            Y[(size_t)trow*DIN + h*128 + p] = acc[i][j] + Dh*xv;
        }
    }
    __syncthreads();

    #pragma unroll
    for (int i = 0; i < 8; i++)
        #pragma unroll
        for (int j = 0; j < 8; j++) acc[i][j] = 0.f;
    float clast = cs[127];
    for (int qt = 0; qt < 4; qt++) {
        #pragma unroll
        for (int i = 0; i < 16; i++) {
            int idx = tid + i*256;
            int q = idx >> 7, p = idx & 127;
            int qq = qt*32 + q;
            float w = expf(clast - cs[qq]) * dts[qq];
            t1[q*129 + p] = w * Xbase[(size_t)(t0+qq)*CONVD + p];
            t2[q*129 + p] = Bbase[(size_t)(t0+qq)*CONVD + p];
        }
        __syncthreads();
        #pragma unroll
        for (int k = 0; k < 32; k++) {
            float xr[8], br[8];
            #pragma unroll
            for (int i = 0; i < 8; i++) xr[i] = t1[k*129 + ty*8 + i];
            #pragma unroll
            for (int j = 0; j < 8; j++) br[j] = t2[k*129 + tx*8 + j];
            #pragma unroll
            for (int i = 0; i < 8; i++)
                #pragma unroll
                for (int j = 0; j < 8; j++)
                    acc[i][j] = fmaf(xr[i], br[j], acc[i][j]);
        }
        __syncthreads();
    }
    size_t sbase = (size_t)blk*HP*HN;
    #pragma unroll
    for (int i = 0; i < 8; i++)
        #pragma unroll
        for (int j = 0; j < 8; j++)
            states[sbase + (size_t)(ty*8+i)*HN + tx*8 + j] = acc[i][j];
}

// ---------------- inter-chunk recurrence ----------------
__global__ void scan_k(const float* __restrict__ states, const float* __restrict__ gm,
                       float* __restrict__ prev)
{
    int bh = blockIdx.x;
    int b = bh >> 5, h = bh & 31;
    int e0 = threadIdx.x;
    float S[16];
    #pragma unroll
    for (int e = 0; e < 16; e++) S[e] = 0.f;
    for (int ch = 0; ch < NCH; ch++) {
        int blk = (b*NCH + ch)*NH + h;
        float gv = gm[blk];
        size_t base = (size_t)blk*HP*HN;
        #pragma unroll
        for (int e = 0; e < 16; e++) {
            int idx = e0 + e*1024;
            prev[base + idx] = S[e];
            S[e] = gv*S[e] + states[base + idx];
        }
    }
}

// ---------------- SSD stage 2 ----------------
__global__ void __launch_bounds__(256)
ssd2_k(const float* __restrict__ xbc, const float* __restrict__ prev,
       const float* __restrict__ csv, float* __restrict__ Y)
{
    __shared__ float t1[128*33];
    __shared__ float t2[128*33];
    __shared__ float cs[128];
    int blk = blockIdx.x;
    int h = blk & 31, ch = (blk >> 5) & 15, b = blk >> 9;
    int t0 = b*LSEQ + ch*128;
    int tid = threadIdx.x, tx = tid & 15, ty = tid >> 4;
    if (tid < 128) cs[tid] = csv[blk*128 + tid];
    float acc[8][8];
    #pragma unroll
    for (int i = 0; i < 8; i++)
        #pragma unroll
        for (int j = 0; j < 8; j++) acc[i][j] = 0.f;
    const float* Cbase = xbc + 2048 + h*128;
    size_t pbase = (size_t)blk*HP*HN;
    for (int nt = 0; nt < 4; nt++) {
        #pragma unroll
        for (int i = 0; i < 16; i++) {
            int idx = tid + i*256;
            int r = idx >> 5, n = idx & 31;
            t1[r*33+n] = Cbase[(size_t)(t0+r)*CONVD + nt*32 + n];
            t2[r*33+n] = prev[pbase + (size_t)r*HN + nt*32 + n];
        }
        __syncthreads();
        #pragma unroll
        for (int n = 0; n < 32; n++) {
            float cr[8], pr[8];
            #pragma unroll
            for (int i = 0; i < 8; i++) cr[i] = t1[(ty*8+i)*33 + n];
            #pragma unroll
            for (int j = 0; j < 8; j++) pr[j] = t2[(tx*8+j)*33 + n];
            #pragma unroll
            for (int i = 0; i < 8; i++)
                #pragma unroll
                for (int j = 0; j < 8; j++)
                    acc[i][j] = fmaf(cr[i], pr[j], acc[i][j]);
        }
        __syncthreads();
    }
    #pragma unroll
    for (int i = 0; i < 8; i++) {
        int q = ty*8 + i;
        float eq = expf(cs[q]);
        #pragma unroll
        for (int j = 0; j < 8; j++) {
            int p = tx*8 + j;
            size_t off = (size_t)(t0+q)*DIN + h*128 + p;
            Y[off] += eq * acc[i][j];
        }
    }
}

// ---------------- y = Y * silu(z)  (tf32-rounded: A of out_proj) ----------------
__global__ void gate_y_k(const float* __restrict__ zx, float* __restrict__ Y)
{
    int idx = blockIdx.x*256 + threadIdx.x;
    int t = idx >> 12, d = idx & 4095;
    float z = zx[(size_t)t*PROJ + d];
    float s = z / (1.f + expf(-z));
    Y[idx] = tf32r(Y[idx] * s);
}

// ---------------- act = silu(gate) * up  (tf32-rounded: A of down_proj) ----------------
__global__ void act_k(float* __restrict__ ga, const float* __restrict__ up)
{
    size_t idx = (size_t)blockIdx.x*256 + threadIdx.x;
    float gv = ga[idx];
    ga[idx] = tf32r((gv / (1.f + expf(-gv))) * up[idx]);
}

// ---------------- launcher ----------------
extern "C" void kernel_launch(void* const* d_in, const int* in_sizes, int n_in,
                              void* d_out, int out_size)
{
    const float* hidden = (const float*)d_in[0];
    const float* w_in   = (const float*)d_in[1];
    const float* conv_w = (const float*)d_in[2];
    const float* conv_b = (const float*)d_in[3];
    const float* A_log  = (const float*)d_in[4];
    const float* Dv     = (const float*)d_in[5];
    const float* dt_b   = (const float*)d_in[6];
    const float* w_out  = (const float*)d_in[7];
    const float* ln1    = (const float*)d_in[8];
    const float* ln2    = (const float*)d_in[9];
    const float* gate_w = (const float*)d_in[10];
    const float* up_w   = (const float*)d_in[11];
    const float* down_w = (const float*)d_in[12];
    float* out = (float*)d_out;

    float *hnorm, *zx, *xbc, *dt, *av, *cs, *gm, *st, *pv, *Y, *h, *h2, *ga, *up;
    cudaGetSymbolAddress((void**)&hnorm, d_hnorm);
    cudaGetSymbolAddress((void**)&zx,    d_zx);
    cudaGetSymbolAddress((void**)&xbc,   d_xbc);
    cudaGetSymbolAddress((void**)&dt,    d_dt);
    cudaGetSymbolAddress((void**)&av,    d_av);
    cudaGetSymbolAddress((void**)&cs,    d_cs);
    cudaGetSymbolAddress((void**)&gm,    d_gm);
    cudaGetSymbolAddress((void**)&st,    d_states);
    cudaGetSymbolAddress((void**)&pv,    d_prev);
    cudaGetSymbolAddress((void**)&Y,     d_Y);
    cudaGetSymbolAddress((void**)&h,     d_h);
    cudaGetSymbolAddress((void**)&h2,    d_h2);
    cudaGetSymbolAddress((void**)&ga,    d_ga);
    cudaGetSymbolAddress((void**)&up,    d_up);

    cudaFuncSetAttribute(gemm_mma, cudaFuncAttributeMaxDynamicSharedMemorySize, GSMEM_DYN);

    // 1) pre-norm (tf32-rounded output)
    rmsnorm_k<<<TKN, 256>>>(hidden, ln1, hnorm);
    // 2) in_proj (tf32 mma.sync tensor cores)
    gemm_mma<<<dim3(81, 32), 256, GSMEM_DYN>>>(hnorm, w_in, nullptr, zx, PROJ, DM);
    // 3) depthwise causal conv + SiLU
    conv_k<<<dim3(24, TKN), 256>>>(zx, conv_w, conv_b, xbc);
    // 4) dt / a
    dt_k<<<(TKN*NH)/256, 256>>>(zx, dt_b, A_log, dt, av);
    // 5) SSD stage 1
    int smem1 = (128*129 + 4224 + 4224 + 128 + 128) * 4;
    cudaFuncSetAttribute(ssd1_k, cudaFuncAttributeMaxDynamicSharedMemorySize, smem1);
    ssd1_k<<<NBLK, 256, smem1>>>(xbc, dt, av, Dv, Y, cs, gm, st);
    // 6) inter-chunk recurrence
    scan_k<<<NB*NH, 1024>>>(st, gm, pv);
    // 7) SSD stage 2
    ssd2_k<<<NBLK, 256>>>(xbc, pv, cs, Y);
    // 8) gate with silu(z)
    gate_y_k<<<(TKN*DIN)/256, 256>>>(zx, Y);
    // 9) out_proj + residual
    gemm_mma<<<dim3(32, 32), 256, GSMEM_DYN>>>(Y, w_out, hidden, h, DM, DIN);
    // 10) second norm (tf32-rounded output)
    rmsnorm_k<<<TKN, 256>>>(h, ln2, h2);
    // 11) MLP
    gemm_mma<<<dim3(112, 32), 256, GSMEM_DYN>>>(h2, gate_w, nullptr, ga, INTERD, DM);
    gemm_mma<<<dim3(112, 32), 256, GSMEM_DYN>>>(h2, up_w,   nullptr, up, INTERD, DM);
    act_k<<<((size_t)TKN*INTERD)/256, 256>>>(ga, up);
    // 12) down_proj + residual -> out
    gemm_mma<<<dim3(32, 32), 256, GSMEM_DYN>>>(ga, down_w, h, out, DM, INTERD);
}